// round 1
// baseline (speedup 1.0000x reference)
#include <cuda_runtime.h>
#include <math.h>

// Problem constants
constexpr int kB  = 8;
constexpr int kS  = 384;
constexpr int kD  = 768;
constexpr int kE  = 768;
constexpr int kH  = 12;
constexpr int kHD = 64;
constexpr int kR  = 2 * kS - 1;   // 767 distinct relative positions actually used

// ---------------------------------------------------------------------------
// Scratch (device globals; no runtime allocation allowed)
// ---------------------------------------------------------------------------
__device__ float g_q[kB * kH * kS * kHD];       // [B,H,S,HD]
__device__ float g_k[kB * kH * kS * kHD];
__device__ float g_v[kB * kH * kS * kHD];
__device__ float g_pk[kH * kR * kHD];           // [H,R,HD]
__device__ float g_pq[kH * kR * kHD];
__device__ float g_logits[(size_t)kB * kH * kS * kS]; // [B,H,S,S]
__device__ float g_vals[kB * kS * kE];          // [B,S,E]

// ---------------------------------------------------------------------------
// Generic GEMM: C[m,n] = sum_k A[m,k] * W[n,k] + bias[n]
// out_mode 0: C[m*N+n]
// out_mode 1: qkv head layout  [B,H,S,HD] with m=b*S+s, n=h*HD+hd
// out_mode 2: pos layout       [H,R,HD]   with m=r,    n=h*HD+hd
// ---------------------------------------------------------------------------
constexpr int GBM = 64, GBN = 64, GBK = 16;

__global__ __launch_bounds__(256) void gemm_bias_kernel(
    const float* __restrict__ A, const float* __restrict__ W,
    const float* __restrict__ bias, float* __restrict__ C,
    int M, int N, int K, int out_mode)
{
    __shared__ __align__(16) float As[GBK][68];
    __shared__ __align__(16) float Ws[GBK][68];

    const int t  = threadIdx.x;
    const int bm = blockIdx.y * GBM;
    const int bn = blockIdx.x * GBN;
    const int tx = t & 15, ty = t >> 4;

    const int lrow = t >> 2;          // 0..63
    const int lc4  = (t & 3) << 2;    // 0,4,8,12

    float acc[4][4] = {};

    for (int k0 = 0; k0 < K; k0 += GBK) {
        float4 av = make_float4(0.f, 0.f, 0.f, 0.f);
        float4 wv = make_float4(0.f, 0.f, 0.f, 0.f);
        if (bm + lrow < M) av = *(const float4*)&A[(size_t)(bm + lrow) * K + k0 + lc4];
        if (bn + lrow < N) wv = *(const float4*)&W[(size_t)(bn + lrow) * K + k0 + lc4];
        __syncthreads();
        As[lc4 + 0][lrow] = av.x; As[lc4 + 1][lrow] = av.y;
        As[lc4 + 2][lrow] = av.z; As[lc4 + 3][lrow] = av.w;
        Ws[lc4 + 0][lrow] = wv.x; Ws[lc4 + 1][lrow] = wv.y;
        Ws[lc4 + 2][lrow] = wv.z; Ws[lc4 + 3][lrow] = wv.w;
        __syncthreads();
#pragma unroll
        for (int kk = 0; kk < GBK; kk++) {
            float4 a4 = *(const float4*)&As[kk][ty << 2];
            float4 b4 = *(const float4*)&Ws[kk][tx << 2];
            float a[4] = {a4.x, a4.y, a4.z, a4.w};
            float b[4] = {b4.x, b4.y, b4.z, b4.w};
#pragma unroll
            for (int ii = 0; ii < 4; ii++)
#pragma unroll
                for (int jj = 0; jj < 4; jj++)
                    acc[ii][jj] += a[ii] * b[jj];
        }
    }

#pragma unroll
    for (int ii = 0; ii < 4; ii++) {
        int m = bm + (ty << 2) + ii;
        if (m >= M) continue;
#pragma unroll
        for (int jj = 0; jj < 4; jj++) {
            int n = bn + (tx << 2) + jj;
            float val = acc[ii][jj] + bias[n];
            if (out_mode == 0) {
                C[(size_t)m * N + n] = val;
            } else if (out_mode == 1) {
                int b = m / kS, s = m % kS, h = n / kHD, hd = n % kHD;
                C[((((size_t)b * kH) + h) * kS + s) * kHD + hd] = val;
            } else {
                int h = n / kHD, hd = n % kHD;
                C[(((size_t)h * kR) + m) * kHD + hd] = val;
            }
        }
    }
}

// ---------------------------------------------------------------------------
// Logits: logits[b,h,i,j] = (q_i.k_j + q_i.pk[i-j+383] + pq[i-j+383].k_j)/sqrt(192)
//                           + segment bias, masked.
// 32x32 tile per block, banded pk/pq window of 63 rows in smem.
// ---------------------------------------------------------------------------
constexpr int LOGITS_SMEM_FLOATS = 2 * (32 * 68) + 2 * (63 * 68); // 12920
constexpr int LOGITS_SMEM_BYTES  = LOGITS_SMEM_FLOATS * 4;        // 51680

__global__ __launch_bounds__(256) void logits_kernel(
    const float* __restrict__ q, const float* __restrict__ k,
    const float* __restrict__ pk, const float* __restrict__ pq,
    const int* __restrict__ mask, const int* __restrict__ seg,
    const float* __restrict__ sep,
    const float* __restrict__ same_bias, const float* __restrict__ cross_bias,
    const float* __restrict__ sep_scale, const float* __restrict__ sep_decay,
    float* __restrict__ logits)
{
    extern __shared__ __align__(16) float sm[];
    float* qs  = sm;                    // 32*68
    float* ks  = qs + 32 * 68;          // 32*68
    float* pks = ks + 32 * 68;          // 63*68
    float* pqs = pks + 63 * 68;         // 63*68

    __shared__ int   s_segi[32], s_segj[32], s_maskj[32];
    __shared__ float s_sepi[32], s_sepj[32];

    const int bh = blockIdx.z, b = bh / kH, h = bh % kH;
    const int i0 = blockIdx.y * 32, j0 = blockIdx.x * 32;
    const int t  = threadIdx.x;
    const int tx = t & 31, ty = t >> 5;
    const int rb = i0 - j0 + 352;       // first pk/pq row of the 63-row window

    const float* qbase = q + (((size_t)b * kH + h) * kS + i0) * kHD;
    const float* kbase = k + (((size_t)b * kH + h) * kS + j0) * kHD;

    for (int l = t; l < 32 * 16; l += 256) {
        int row = l >> 4, c4 = (l & 15) << 2;
        *(float4*)&qs[row * 68 + c4] = *(const float4*)&qbase[row * kHD + c4];
        *(float4*)&ks[row * 68 + c4] = *(const float4*)&kbase[row * kHD + c4];
    }
    for (int l = t; l < 63 * 16; l += 256) {
        int row = l >> 4, c4 = (l & 15) << 2;
        size_t g = (((size_t)h * kR) + rb + row) * kHD + c4;
        *(float4*)&pks[row * 68 + c4] = *(const float4*)&pk[g];
        *(float4*)&pqs[row * 68 + c4] = *(const float4*)&pq[g];
    }
    if (t < 32) {
        s_segi[t]  = seg[b * kS + i0 + t];
        s_segj[t]  = seg[b * kS + j0 + t];
        s_sepi[t]  = fabsf(sep[b * kS + i0 + t]);
        s_sepj[t]  = fabsf(sep[b * kS + j0 + t]);
        s_maskj[t] = mask[b * kS + j0 + t];
    }
    __syncthreads();

    float c2c[4] = {}, c2p[4] = {}, p2c[4] = {};
#pragma unroll
    for (int d = 0; d < kHD; d += 4) {
        float4 kv = *(const float4*)&ks[tx * 68 + d];
#pragma unroll
        for (int w = 0; w < 4; w++) {
            int il = ty + (w << 3);
            float4 qv  = *(const float4*)&qs[il * 68 + d];
            int    rl  = il - tx + 31;   // 0..62
            float4 pkv = *(const float4*)&pks[rl * 68 + d];
            float4 pqv = *(const float4*)&pqs[rl * 68 + d];
            c2c[w] += qv.x * kv.x + qv.y * kv.y + qv.z * kv.z + qv.w * kv.w;
            c2p[w] += qv.x * pkv.x + qv.y * pkv.y + qv.z * pkv.z + qv.w * pkv.w;
            p2c[w] += pqv.x * kv.x + pqv.y * kv.y + pqv.z * kv.z + pqv.w * kv.w;
        }
    }

    const float sb_same  = same_bias[h];
    const float sb_cross = cross_bias[h];
    const float scale_h  = sep_scale[h];
    const float dx       = sep_decay[h];
    const float softp    = fmaxf(dx, 0.f) + log1pf(expf(-fabsf(dx)));
    const float decay    = softp + 1e-4f;
    const float inv      = 0.07216878364870322f;  // 1/sqrt(3*HD)

    const int   j    = j0 + tx;
    const int   segj = s_segj[tx];
    const float sepj = s_sepj[tx];
    const int   mj   = s_maskj[tx];

#pragma unroll
    for (int w = 0; w < 4; w++) {
        int il = ty + (w << 3);
        int i  = i0 + il;
        float val = (c2c[w] + c2p[w] + p2c[w]) * inv;
        if (s_segi[il] == segj) {
            val += sb_same;
        } else {
            float gap = fabsf(s_sepi[il] - sepj);
            val += sb_cross + expf(-gap * decay) * scale_h;
        }
        if (mj == 0) val = -9e15f;
        logits[(((size_t)bh * kS) + i) * kS + j] = val;
    }
}

// ---------------------------------------------------------------------------
// Row softmax over S=384, one block of 128 threads per row
// ---------------------------------------------------------------------------
__global__ __launch_bounds__(128) void softmax_kernel(float* __restrict__ logits)
{
    const size_t row = blockIdx.x;
    float* p = logits + row * kS;
    const int t = threadIdx.x;

    float v0 = p[t], v1 = p[t + 128], v2 = p[t + 256];
    float m = fmaxf(v0, fmaxf(v1, v2));

    __shared__ float red[4];
#pragma unroll
    for (int o = 16; o; o >>= 1) m = fmaxf(m, __shfl_xor_sync(0xffffffffu, m, o));
    if ((t & 31) == 0) red[t >> 5] = m;
    __syncthreads();
    m = fmaxf(fmaxf(red[0], red[1]), fmaxf(red[2], red[3]));

    float e0 = expf(v0 - m), e1 = expf(v1 - m), e2 = expf(v2 - m);
    float s = e0 + e1 + e2;
#pragma unroll
    for (int o = 16; o; o >>= 1) s += __shfl_xor_sync(0xffffffffu, s, o);
    __shared__ float red2[4];
    if ((t & 31) == 0) red2[t >> 5] = s;
    __syncthreads();
    s = red2[0] + red2[1] + red2[2] + red2[3];

    float r = 1.f / s;
    p[t] = e0 * r; p[t + 128] = e1 * r; p[t + 256] = e2 * r;
}

// ---------------------------------------------------------------------------
// AV: vals[b,i,h*HD+d] = sum_j attn[b,h,i,j] * v[b,h,j,d]
// 64 rows x 64 cols per block, K-tiles of 32
// ---------------------------------------------------------------------------
__global__ __launch_bounds__(256) void av_kernel(
    const float* __restrict__ attn, const float* __restrict__ v,
    float* __restrict__ vals)
{
    __shared__ __align__(16) float As[32][68];  // [k][m]
    __shared__ __align__(16) float Vs[32][68];  // [k][n]

    const int bh = blockIdx.y, b = bh / kH, h = bh % kH;
    const int i0 = blockIdx.x * 64;
    const float* A = attn + (size_t)bh * kS * kS;
    const float* V = v + (size_t)bh * kS * kHD;

    const int t  = threadIdx.x;
    const int tx = t & 15, ty = t >> 4;

    float acc[4][4] = {};

    for (int k0 = 0; k0 < kS; k0 += 32) {
        float4 ar[2], vr[2];
#pragma unroll
        for (int l = 0; l < 2; l++) {
            int lin = t + 256 * l;
            int arow = lin >> 3, ac4 = (lin & 7) << 2;   // 64 x 32 tile
            ar[l] = *(const float4*)&A[(size_t)(i0 + arow) * kS + k0 + ac4];
            int vrow = lin >> 4, vc4 = (lin & 15) << 2;  // 32 x 64 tile
            vr[l] = *(const float4*)&V[(size_t)(k0 + vrow) * kHD + vc4];
        }
        __syncthreads();
#pragma unroll
        for (int l = 0; l < 2; l++) {
            int lin = t + 256 * l;
            int arow = lin >> 3, ac4 = (lin & 7) << 2;
            As[ac4 + 0][arow] = ar[l].x; As[ac4 + 1][arow] = ar[l].y;
            As[ac4 + 2][arow] = ar[l].z; As[ac4 + 3][arow] = ar[l].w;
            int vrow = lin >> 4, vc4 = (lin & 15) << 2;
            *(float4*)&Vs[vrow][vc4] = vr[l];
        }
        __syncthreads();
#pragma unroll
        for (int kk = 0; kk < 32; kk++) {
            float4 a4 = *(const float4*)&As[kk][ty << 2];
            float4 b4 = *(const float4*)&Vs[kk][tx << 2];
            float a[4] = {a4.x, a4.y, a4.z, a4.w};
            float bb[4] = {b4.x, b4.y, b4.z, b4.w};
#pragma unroll
            for (int ii = 0; ii < 4; ii++)
#pragma unroll
                for (int jj = 0; jj < 4; jj++)
                    acc[ii][jj] += a[ii] * bb[jj];
        }
    }

#pragma unroll
    for (int ii = 0; ii < 4; ii++) {
        int i = i0 + (ty << 2) + ii;
#pragma unroll
        for (int jj = 0; jj < 4; jj++) {
            int d = (tx << 2) + jj;
            vals[((size_t)b * kS + i) * kE + h * kHD + d] = acc[ii][jj];
        }
    }
}

// ---------------------------------------------------------------------------
// Launch
// ---------------------------------------------------------------------------
extern "C" void kernel_launch(void* const* d_in, const int* in_sizes, int n_in,
                              void* d_out, int out_size)
{
    const float* x    = (const float*)d_in[0];
    const int*   mask = (const int*)d_in[1];
    const int*   seg  = (const int*)d_in[2];
    const float* sep  = (const float*)d_in[3];
    const float* Wq   = (const float*)d_in[4];
    const float* bq   = (const float*)d_in[5];
    const float* Wk   = (const float*)d_in[6];
    const float* bk   = (const float*)d_in[7];
    const float* Wv   = (const float*)d_in[8];
    const float* bv   = (const float*)d_in[9];
    const float* rel  = (const float*)d_in[10];
    const float* Wpk  = (const float*)d_in[11];
    const float* bpk  = (const float*)d_in[12];
    const float* Wpq  = (const float*)d_in[13];
    const float* bpq  = (const float*)d_in[14];
    const float* same_b  = (const float*)d_in[15];
    const float* cross_b = (const float*)d_in[16];
    const float* sscale  = (const float*)d_in[17];
    const float* sdecay  = (const float*)d_in[18];
    const float* Wo   = (const float*)d_in[19];
    const float* bo   = (const float*)d_in[20];
    float* out = (float*)d_out;

    float *q_, *k_, *v_, *pk_, *pq_, *lg_, *vl_;
    cudaGetSymbolAddress((void**)&q_,  g_q);
    cudaGetSymbolAddress((void**)&k_,  g_k);
    cudaGetSymbolAddress((void**)&v_,  g_v);
    cudaGetSymbolAddress((void**)&pk_, g_pk);
    cudaGetSymbolAddress((void**)&pq_, g_pq);
    cudaGetSymbolAddress((void**)&lg_, g_logits);
    cudaGetSymbolAddress((void**)&vl_, g_vals);

    cudaFuncSetAttribute(logits_kernel,
                         cudaFuncAttributeMaxDynamicSharedMemorySize,
                         LOGITS_SMEM_BYTES);

    // 1) Q, K, V projections  ([B*S,D] @ [E,D]^T) -> [B,H,S,HD]
    dim3 gproj(kE / GBN, (kB * kS) / GBM);
    gemm_bias_kernel<<<gproj, 256>>>(x, Wq, bq, q_, kB * kS, kE, kD, 1);
    gemm_bias_kernel<<<gproj, 256>>>(x, Wk, bk, k_, kB * kS, kE, kD, 1);
    gemm_bias_kernel<<<gproj, 256>>>(x, Wv, bv, v_, kB * kS, kE, kD, 1);

    // 2) Positional projections: rows 128..894 of rel_emb -> [H,R,HD]
    dim3 gpos(kE / GBN, (kR + GBM - 1) / GBM);
    const float* relbase = rel + (size_t)128 * kD;
    gemm_bias_kernel<<<gpos, 256>>>(relbase, Wpk, bpk, pk_, kR, kE, kD, 2);
    gemm_bias_kernel<<<gpos, 256>>>(relbase, Wpq, bpq, pq_, kR, kE, kD, 2);

    // 3) Logits + segment bias + mask
    dim3 glog(kS / 32, kS / 32, kB * kH);
    logits_kernel<<<glog, 256, LOGITS_SMEM_BYTES>>>(
        q_, k_, pk_, pq_, mask, seg, sep,
        same_b, cross_b, sscale, sdecay, lg_);

    // 4) Softmax over keys
    softmax_kernel<<<kB * kH * kS, 128>>>(lg_);

    // 5) attn @ V -> vals [B,S,E]
    dim3 gav(kS / 64, kB * kH);
    av_kernel<<<gav, 256>>>(lg_, v_, vl_);

    // 6) Output projection: vals @ Wo^T + bo -> [B,S,D]
    dim3 gout(kD / GBN, (kB * kS) / GBM);
    gemm_bias_kernel<<<gout, 256>>>(vl_, Wo, bo, out, kB * kS, kD, kE, 0);
}

// round 2
// speedup vs baseline: 1.0030x; 1.0030x over previous
#include <cuda_runtime.h>
#include <math.h>

// Problem constants
constexpr int kB  = 8;
constexpr int kS  = 384;
constexpr int kD  = 768;
constexpr int kE  = 768;
constexpr int kH  = 12;
constexpr int kHD = 64;
constexpr int kR  = 2 * kS - 1;   // 767 distinct relative positions actually used

// ---------------------------------------------------------------------------
// Scratch (device globals; no runtime allocation allowed)
// ---------------------------------------------------------------------------
__device__ float g_q[kB * kH * kS * kHD];       // [B,H,S,HD]
__device__ float g_k[kB * kH * kS * kHD];
__device__ float g_v[kB * kH * kS * kHD];
__device__ float g_pk[kH * kR * kHD];           // [H,R,HD]
__device__ float g_pq[kH * kR * kHD];
__device__ float g_logits[(size_t)kB * kH * kS * kS]; // [B,H,S,S]
__device__ float g_vals[kB * kS * kE];          // [B,S,E]

// ---------------------------------------------------------------------------
// Generic GEMM: C[m,n] = sum_k A[m,k] * W[n,k] + bias[n]
// out_mode 0: C[m*N+n]
// out_mode 1: qkv head layout  [B,H,S,HD] with m=b*S+s, n=h*HD+hd
// out_mode 2: pos layout       [H,R,HD]   with m=r,    n=h*HD+hd
// ---------------------------------------------------------------------------
constexpr int GBM = 64, GBN = 64, GBK = 16;

__global__ __launch_bounds__(256) void gemm_bias_kernel(
    const float* __restrict__ A, const float* __restrict__ W,
    const float* __restrict__ bias, float* __restrict__ C,
    int M, int N, int K, int out_mode)
{
    __shared__ __align__(16) float As[GBK][68];
    __shared__ __align__(16) float Ws[GBK][68];

    const int t  = threadIdx.x;
    const int bm = blockIdx.y * GBM;
    const int bn = blockIdx.x * GBN;
    const int tx = t & 15, ty = t >> 4;

    const int lrow = t >> 2;          // 0..63
    const int lc4  = (t & 3) << 2;    // 0,4,8,12

    float acc[4][4] = {};

    for (int k0 = 0; k0 < K; k0 += GBK) {
        float4 av = make_float4(0.f, 0.f, 0.f, 0.f);
        float4 wv = make_float4(0.f, 0.f, 0.f, 0.f);
        if (bm + lrow < M) av = *(const float4*)&A[(size_t)(bm + lrow) * K + k0 + lc4];
        if (bn + lrow < N) wv = *(const float4*)&W[(size_t)(bn + lrow) * K + k0 + lc4];
        __syncthreads();
        As[lc4 + 0][lrow] = av.x; As[lc4 + 1][lrow] = av.y;
        As[lc4 + 2][lrow] = av.z; As[lc4 + 3][lrow] = av.w;
        Ws[lc4 + 0][lrow] = wv.x; Ws[lc4 + 1][lrow] = wv.y;
        Ws[lc4 + 2][lrow] = wv.z; Ws[lc4 + 3][lrow] = wv.w;
        __syncthreads();
#pragma unroll
        for (int kk = 0; kk < GBK; kk++) {
            float4 a4 = *(const float4*)&As[kk][ty << 2];
            float4 b4 = *(const float4*)&Ws[kk][tx << 2];
            float a[4] = {a4.x, a4.y, a4.z, a4.w};
            float b[4] = {b4.x, b4.y, b4.z, b4.w};
#pragma unroll
            for (int ii = 0; ii < 4; ii++)
#pragma unroll
                for (int jj = 0; jj < 4; jj++)
                    acc[ii][jj] += a[ii] * b[jj];
        }
    }

#pragma unroll
    for (int ii = 0; ii < 4; ii++) {
        int m = bm + (ty << 2) + ii;
        if (m >= M) continue;
#pragma unroll
        for (int jj = 0; jj < 4; jj++) {
            int n = bn + (tx << 2) + jj;
            float val = acc[ii][jj] + bias[n];
            if (out_mode == 0) {
                C[(size_t)m * N + n] = val;
            } else if (out_mode == 1) {
                int b = m / kS, s = m % kS, h = n / kHD, hd = n % kHD;
                C[((((size_t)b * kH) + h) * kS + s) * kHD + hd] = val;
            } else {
                int h = n / kHD, hd = n % kHD;
                C[(((size_t)h * kR) + m) * kHD + hd] = val;
            }
        }
    }
}

// ---------------------------------------------------------------------------
// Logits: logits[b,h,i,j] = (q_i.k_j + q_i.pk[i-j+383] + pq[i-j+383].k_j)/sqrt(192)
//                           + segment bias, masked.
// 32x32 tile per block, banded pk/pq window of 63 rows in smem.
// ---------------------------------------------------------------------------
constexpr int LOGITS_SMEM_FLOATS = 2 * (32 * 68) + 2 * (63 * 68); // 12920
constexpr int LOGITS_SMEM_BYTES  = LOGITS_SMEM_FLOATS * 4;        // 51680

__global__ __launch_bounds__(256) void logits_kernel(
    const float* __restrict__ q, const float* __restrict__ k,
    const float* __restrict__ pk, const float* __restrict__ pq,
    const int* __restrict__ mask, const int* __restrict__ seg,
    const float* __restrict__ sep,
    const float* __restrict__ same_bias, const float* __restrict__ cross_bias,
    const float* __restrict__ sep_scale, const float* __restrict__ sep_decay,
    float* __restrict__ logits)
{
    extern __shared__ __align__(16) float sm[];
    float* qs  = sm;                    // 32*68
    float* ks  = qs + 32 * 68;          // 32*68
    float* pks = ks + 32 * 68;          // 63*68
    float* pqs = pks + 63 * 68;         // 63*68

    __shared__ int   s_segi[32], s_segj[32], s_maskj[32];
    __shared__ float s_sepi[32], s_sepj[32];

    const int bh = blockIdx.z, b = bh / kH, h = bh % kH;
    const int i0 = blockIdx.y * 32, j0 = blockIdx.x * 32;
    const int t  = threadIdx.x;
    const int tx = t & 31, ty = t >> 5;
    const int rb = i0 - j0 + 352;       // first pk/pq row of the 63-row window

    const float* qbase = q + (((size_t)b * kH + h) * kS + i0) * kHD;
    const float* kbase = k + (((size_t)b * kH + h) * kS + j0) * kHD;

    for (int l = t; l < 32 * 16; l += 256) {
        int row = l >> 4, c4 = (l & 15) << 2;
        *(float4*)&qs[row * 68 + c4] = *(const float4*)&qbase[row * kHD + c4];
        *(float4*)&ks[row * 68 + c4] = *(const float4*)&kbase[row * kHD + c4];
    }
    for (int l = t; l < 63 * 16; l += 256) {
        int row = l >> 4, c4 = (l & 15) << 2;
        size_t g = (((size_t)h * kR) + rb + row) * kHD + c4;
        *(float4*)&pks[row * 68 + c4] = *(const float4*)&pk[g];
        *(float4*)&pqs[row * 68 + c4] = *(const float4*)&pq[g];
    }
    if (t < 32) {
        s_segi[t]  = seg[b * kS + i0 + t];
        s_segj[t]  = seg[b * kS + j0 + t];
        s_sepi[t]  = fabsf(sep[b * kS + i0 + t]);
        s_sepj[t]  = fabsf(sep[b * kS + j0 + t]);
        s_maskj[t] = mask[b * kS + j0 + t];
    }
    __syncthreads();

    float c2c[4] = {}, c2p[4] = {}, p2c[4] = {};
#pragma unroll
    for (int d = 0; d < kHD; d += 4) {
        float4 kv = *(const float4*)&ks[tx * 68 + d];
#pragma unroll
        for (int w = 0; w < 4; w++) {
            int il = ty + (w << 3);
            float4 qv  = *(const float4*)&qs[il * 68 + d];
            int    rl  = il - tx + 31;   // 0..62
            float4 pkv = *(const float4*)&pks[rl * 68 + d];
            float4 pqv = *(const float4*)&pqs[rl * 68 + d];
            c2c[w] += qv.x * kv.x + qv.y * kv.y + qv.z * kv.z + qv.w * kv.w;
            c2p[w] += qv.x * pkv.x + qv.y * pkv.y + qv.z * pkv.z + qv.w * pkv.w;
            p2c[w] += pqv.x * kv.x + pqv.y * kv.y + pqv.z * kv.z + pqv.w * kv.w;
        }
    }

    const float sb_same  = same_bias[h];
    const float sb_cross = cross_bias[h];
    const float scale_h  = sep_scale[h];
    const float dx       = sep_decay[h];
    const float softp    = fmaxf(dx, 0.f) + log1pf(expf(-fabsf(dx)));
    const float decay    = softp + 1e-4f;
    const float inv      = 0.07216878364870322f;  // 1/sqrt(3*HD)

    const int   j    = j0 + tx;
    const int   segj = s_segj[tx];
    const float sepj = s_sepj[tx];
    const int   mj   = s_maskj[tx];

#pragma unroll
    for (int w = 0; w < 4; w++) {
        int il = ty + (w << 3);
        int i  = i0 + il;
        float val = (c2c[w] + c2p[w] + p2c[w]) * inv;
        if (s_segi[il] == segj) {
            val += sb_same;
        } else {
            float gap = fabsf(s_sepi[il] - sepj);
            val += sb_cross + expf(-gap * decay) * scale_h;
        }
        if (mj == 0) val = -9e15f;
        logits[(((size_t)bh * kS) + i) * kS + j] = val;
    }
}

// ---------------------------------------------------------------------------
// Row softmax over S=384, one block of 128 threads per row
// ---------------------------------------------------------------------------
__global__ __launch_bounds__(128) void softmax_kernel(float* __restrict__ logits)
{
    const size_t row = blockIdx.x;
    float* p = logits + row * kS;
    const int t = threadIdx.x;

    float v0 = p[t], v1 = p[t + 128], v2 = p[t + 256];
    float m = fmaxf(v0, fmaxf(v1, v2));

    __shared__ float red[4];
#pragma unroll
    for (int o = 16; o; o >>= 1) m = fmaxf(m, __shfl_xor_sync(0xffffffffu, m, o));
    if ((t & 31) == 0) red[t >> 5] = m;
    __syncthreads();
    m = fmaxf(fmaxf(red[0], red[1]), fmaxf(red[2], red[3]));

    float e0 = expf(v0 - m), e1 = expf(v1 - m), e2 = expf(v2 - m);
    float s = e0 + e1 + e2;
#pragma unroll
    for (int o = 16; o; o >>= 1) s += __shfl_xor_sync(0xffffffffu, s, o);
    __shared__ float red2[4];
    if ((t & 31) == 0) red2[t >> 5] = s;
    __syncthreads();
    s = red2[0] + red2[1] + red2[2] + red2[3];

    float r = 1.f / s;
    p[t] = e0 * r; p[t + 128] = e1 * r; p[t + 256] = e2 * r;
}

// ---------------------------------------------------------------------------
// AV: vals[b,i,h*HD+d] = sum_j attn[b,h,i,j] * v[b,h,j,d]
// 64 rows x 64 cols per block, K-tiles of 32
// ---------------------------------------------------------------------------
__global__ __launch_bounds__(256) void av_kernel(
    const float* __restrict__ attn, const float* __restrict__ v,
    float* __restrict__ vals)
{
    __shared__ __align__(16) float As[32][68];  // [k][m]
    __shared__ __align__(16) float Vs[32][68];  // [k][n]

    const int bh = blockIdx.y, b = bh / kH, h = bh % kH;
    const int i0 = blockIdx.x * 64;
    const float* A = attn + (size_t)bh * kS * kS;
    const float* V = v + (size_t)bh * kS * kHD;

    const int t  = threadIdx.x;
    const int tx = t & 15, ty = t >> 4;

    float acc[4][4] = {};

    for (int k0 = 0; k0 < kS; k0 += 32) {
        float4 ar[2], vr[2];
#pragma unroll
        for (int l = 0; l < 2; l++) {
            int lin = t + 256 * l;
            int arow = lin >> 3, ac4 = (lin & 7) << 2;   // 64 x 32 tile
            ar[l] = *(const float4*)&A[(size_t)(i0 + arow) * kS + k0 + ac4];
            int vrow = lin >> 4, vc4 = (lin & 15) << 2;  // 32 x 64 tile
            vr[l] = *(const float4*)&V[(size_t)(k0 + vrow) * kHD + vc4];
        }
        __syncthreads();
#pragma unroll
        for (int l = 0; l < 2; l++) {
            int lin = t + 256 * l;
            int arow = lin >> 3, ac4 = (lin & 7) << 2;
            As[ac4 + 0][arow] = ar[l].x; As[ac4 + 1][arow] = ar[l].y;
            As[ac4 + 2][arow] = ar[l].z; As[ac4 + 3][arow] = ar[l].w;
            int vrow = lin >> 4, vc4 = (lin & 15) << 2;
            *(float4*)&Vs[vrow][vc4] = vr[l];
        }
        __syncthreads();
#pragma unroll
        for (int kk = 0; kk < 32; kk++) {
            float4 a4 = *(const float4*)&As[kk][ty << 2];
            float4 b4 = *(const float4*)&Vs[kk][tx << 2];
            float a[4] = {a4.x, a4.y, a4.z, a4.w};
            float bb[4] = {b4.x, b4.y, b4.z, b4.w};
#pragma unroll
            for (int ii = 0; ii < 4; ii++)
#pragma unroll
                for (int jj = 0; jj < 4; jj++)
                    acc[ii][jj] += a[ii] * bb[jj];
        }
    }

#pragma unroll
    for (int ii = 0; ii < 4; ii++) {
        int i = i0 + (ty << 2) + ii;
#pragma unroll
        for (int jj = 0; jj < 4; jj++) {
            int d = (tx << 2) + jj;
            vals[((size_t)b * kS + i) * kE + h * kHD + d] = acc[ii][jj];
        }
    }
}

// ---------------------------------------------------------------------------
// Launch
// ---------------------------------------------------------------------------
extern "C" void kernel_launch(void* const* d_in, const int* in_sizes, int n_in,
                              void* d_out, int out_size)
{
    const float* x    = (const float*)d_in[0];
    const int*   mask = (const int*)d_in[1];
    const int*   seg  = (const int*)d_in[2];
    const float* sep  = (const float*)d_in[3];
    const float* Wq   = (const float*)d_in[4];
    const float* bq   = (const float*)d_in[5];
    const float* Wk   = (const float*)d_in[6];
    const float* bk   = (const float*)d_in[7];
    const float* Wv   = (const float*)d_in[8];
    const float* bv   = (const float*)d_in[9];
    const float* rel  = (const float*)d_in[10];
    const float* Wpk  = (const float*)d_in[11];
    const float* bpk  = (const float*)d_in[12];
    const float* Wpq  = (const float*)d_in[13];
    const float* bpq  = (const float*)d_in[14];
    const float* same_b  = (const float*)d_in[15];
    const float* cross_b = (const float*)d_in[16];
    const float* sscale  = (const float*)d_in[17];
    const float* sdecay  = (const float*)d_in[18];
    const float* Wo   = (const float*)d_in[19];
    const float* bo   = (const float*)d_in[20];
    float* out = (float*)d_out;

    float *q_, *k_, *v_, *pk_, *pq_, *lg_, *vl_;
    cudaGetSymbolAddress((void**)&q_,  g_q);
    cudaGetSymbolAddress((void**)&k_,  g_k);
    cudaGetSymbolAddress((void**)&v_,  g_v);
    cudaGetSymbolAddress((void**)&pk_, g_pk);
    cudaGetSymbolAddress((void**)&pq_, g_pq);
    cudaGetSymbolAddress((void**)&lg_, g_logits);
    cudaGetSymbolAddress((void**)&vl_, g_vals);

    cudaFuncSetAttribute(logits_kernel,
                         cudaFuncAttributeMaxDynamicSharedMemorySize,
                         LOGITS_SMEM_BYTES);

    // 1) Q, K, V projections  ([B*S,D] @ [E,D]^T) -> [B,H,S,HD]
    dim3 gproj(kE / GBN, (kB * kS) / GBM);
    gemm_bias_kernel<<<gproj, 256>>>(x, Wq, bq, q_, kB * kS, kE, kD, 1);
    gemm_bias_kernel<<<gproj, 256>>>(x, Wk, bk, k_, kB * kS, kE, kD, 1);
    gemm_bias_kernel<<<gproj, 256>>>(x, Wv, bv, v_, kB * kS, kE, kD, 1);

    // 2) Positional projections: rows 128..894 of rel_emb -> [H,R,HD]
    dim3 gpos(kE / GBN, (kR + GBM - 1) / GBM);
    const float* relbase = rel + (size_t)128 * kD;
    gemm_bias_kernel<<<gpos, 256>>>(relbase, Wpk, bpk, pk_, kR, kE, kD, 2);
    gemm_bias_kernel<<<gpos, 256>>>(relbase, Wpq, bpq, pq_, kR, kE, kD, 2);

    // 3) Logits + segment bias + mask
    dim3 glog(kS / 32, kS / 32, kB * kH);
    logits_kernel<<<glog, 256, LOGITS_SMEM_BYTES>>>(
        q_, k_, pk_, pq_, mask, seg, sep,
        same_b, cross_b, sscale, sdecay, lg_);

    // 4) Softmax over keys
    softmax_kernel<<<kB * kH * kS, 128>>>(lg_);

    // 5) attn @ V -> vals [B,S,E]
    dim3 gav(kS / 64, kB * kH);
    av_kernel<<<gav, 256>>>(lg_, v_, vl_);

    // 6) Output projection: vals @ Wo^T + bo -> [B,S,D]
    dim3 gout(kD / GBN, (kB * kS) / GBM);
    gemm_bias_kernel<<<gout, 256>>>(vl_, Wo, bo, out, kB * kS, kD, kE, 0);
}